// round 15
// baseline (speedup 1.0000x reference)
#include <cuda_runtime.h>
#include <cuda_fp16.h>
#include <cstdint>

#define NTHREADS 1024
#define TILE_M   32
#define NGROUPS  4

// half-element strides (conflict-free ldmatrix / stores)
#define SW2 264   // W2h [128][256+pad]
#define SW1 136   // W1h [48][128+pad]
#define SA   56   // A1h [32][48+pad]
#define SHH 136   // Hh  [32][128+pad]

// smem byte offsets
#define OFF_W2   0              // 128*264*2 = 67584
#define OFF_W1   67584          // 48*136*2  = 13056
#define OFF_GRP  80640          // per-group region base
#define G_A1     0              // 3584 B
#define G_H      3584           // 8704 B
#define G_PS     12288          // 2048 B
#define GRP_SZ   14336
#define OFF_CN   137984         // 992 floats = 3968 B
#define SMEM_BYTES 141952

// CN float offsets
#define C_B1  96
#define C_B2  224
#define C_G2  480
#define C_BB2 736

__device__ __forceinline__ unsigned su32(const void* p) {
    return (unsigned)__cvta_generic_to_shared(p);
}

// tanh-based GELU: HW tanh.approx; error << fp16 rounding of H
__device__ __forceinline__ float gelu_fast(float x) {
    float u = 0.7978845608028654f * fmaf(0.044715f * x, x * x, x);
    float t;
    asm("tanh.approx.f32 %0, %1;" : "=f"(t) : "f"(u));
    return 0.5f * x * (1.0f + t);
}

#define LDM_X4(R, addr)                                                        \
    asm volatile("ldmatrix.sync.aligned.m8n8.x4.shared.b16 {%0,%1,%2,%3}, [%4];" \
        : "=r"((R)[0]), "=r"((R)[1]), "=r"((R)[2]), "=r"((R)[3]) : "r"(addr))

#define LDM_X4T(R, addr)                                                       \
    asm volatile("ldmatrix.sync.aligned.m8n8.x4.trans.shared.b16 {%0,%1,%2,%3}, [%4];" \
        : "=r"((R)[0]), "=r"((R)[1]), "=r"((R)[2]), "=r"((R)[3]) : "r"(addr))

#define MMA_F16(C, A, b0, b1)                                                  \
    asm volatile("mma.sync.aligned.m16n8k16.row.col.f32.f16.f16.f32 "          \
        "{%0,%1,%2,%3}, {%4,%5,%6,%7}, {%8,%9}, {%0,%1,%2,%3};"                \
        : "+f"((C)[0]), "+f"((C)[1]), "+f"((C)[2]), "+f"((C)[3])               \
        : "r"((A)[0]), "r"((A)[1]), "r"((A)[2]), "r"((A)[3]), "r"(b0), "r"(b1))

// group-scoped barrier: 256 threads, ids 1..4
#define BARG(id) asm volatile("bar.sync %0, 256;" :: "r"(id) : "memory")

__global__ void __launch_bounds__(NTHREADS, 1)
pose_mlp_kernel(const float* __restrict__ pose,
                const float* __restrict__ ln1g, const float* __restrict__ ln1b,
                const float* __restrict__ w1,   const float* __restrict__ b1,
                const float* __restrict__ w2,   const float* __restrict__ b2,
                const float* __restrict__ ln2g, const float* __restrict__ ln2b,
                float* __restrict__ out, int ntiles)
{
    extern __shared__ char smem[];
    __half* W2h = (__half*)(smem + OFF_W2);
    __half* W1h = (__half*)(smem + OFF_W1);
    float*  CN  = (float*)(smem + OFF_CN);

    const int tid  = threadIdx.x;
    const int lane = tid & 31;
    const int warp = tid >> 5;
    const int gr   = warp >> 3;           // pipeline group 0..3
    const int wc   = warp & 7;            // warp col (8), Wr = 1
    const int tid2 = tid & 255;           // thread within group
    const int g    = lane >> 2;
    const int t4   = lane & 3;
    const int bid  = gr + 1;              // named barrier id

    char* gbase = smem + OFF_GRP + gr * GRP_SZ;
    __half* A1h = (__half*)(gbase + G_A1);
    __half* Hh  = (__half*)(gbase + G_H);
    float2* PS  = (float2*)(gbase + G_PS);
    const float4* PS4 = (const float4*)(gbase + G_PS);

    const int lm_m  = lane >> 3;
    const int lm_r  = lane & 7;
    const int a_row = lm_r + (lm_m & 1) * 8;
    const int a_kof = (lm_m >> 1) * 8;
    const int b_kof = lm_r + (lm_m & 1) * 8;
    const int b_cof = (lm_m >> 1) * 8;

    // LN1: 8 threads per row (within group), 6 cols each
    const int ln_r  = tid2 >> 3;
    const int ln_c0 = (tid2 & 7) * 6;

    // ---- one-time: weights + consts -> smem (whole CTA) ----
    for (int i = tid; i < 8192; i += NTHREADS) {            // W2 via float4
        int k = i >> 6;
        int c = (i & 63) << 2;
        float4 v = reinterpret_cast<const float4*>(w2)[i];
        __half2* d = (__half2*)&W2h[k * SW2 + c];
        d[0] = __floats2half2_rn(v.x, v.y);
        d[1] = __floats2half2_rn(v.z, v.w);
    }
    for (int i = tid; i < 48 * 128; i += NTHREADS) {        // W1 (gamma-folded), rows 45..47 zero
        int k = i >> 7;
        int c = i & 127;
        W1h[k * SW1 + c] = (k < 45) ? __float2half_rn(ln1g[k] * w1[k * 128 + c])
                                    : __float2half_rn(0.0f);
    }
    if (tid < 128) {                                        // b1' = b1 + ln1b . W1
        float acc = b1[tid];
        for (int k = 0; k < 45; k++) acc += ln1b[k] * w1[k * 128 + tid];
        CN[C_B1 + tid] = acc;
    }
    if (tid >= 128 && tid < 384) {
        int i = tid - 128;
        CN[C_B2 + i] = b2[i]; CN[C_G2 + i] = ln2g[i]; CN[C_BB2 + i] = ln2b[i];
    }
    __syncthreads();   // only CTA-wide barrier; groups independent after this

    const int stride = NGROUPS * gridDim.x;
    int tile = blockIdx.x * NGROUPS + gr;

    // ---- prologue LN1 (gmem -> A1h), gamma/beta folded into W1/b1' ----
    if (tile < ntiles) {
        const float* row = pose + ((size_t)tile * TILE_M + ln_r) * 45;
        float x[6]; float s = 0.f, q = 0.f;
        #pragma unroll
        for (int j = 0; j < 6; j++) {
            int c = ln_c0 + j;
            x[j] = (c < 45) ? row[c] : 0.f;
            s += x[j]; q += x[j] * x[j];
        }
        #pragma unroll
        for (int off = 1; off <= 4; off <<= 1) {
            s += __shfl_xor_sync(0xffffffffu, s, off);
            q += __shfl_xor_sync(0xffffffffu, q, off);
        }
        float mu   = s * (1.0f / 45.0f);
        float var  = q * (1.0f / 45.0f) - mu * mu;
        float rstd = rsqrtf(fmaxf(var, 0.f) + 1e-5f);
        __half2* dstp = (__half2*)&A1h[ln_r * SA + ln_c0];
        #pragma unroll
        for (int j2 = 0; j2 < 3; j2++) {
            dstp[j2] = __floats2half2_rn((x[2*j2]   - mu) * rstd,
                                         (x[2*j2+1] - mu) * rstd);
        }
    }

    for (; tile < ntiles; tile += stride) {
        const int tn = tile + stride;
        BARG(bid);   // A1h ready

        // ---- GEMM1: [32x48] x [48x128], 16 cols/warp (bias folded) ----
        float acc1[2][2][4];
        #pragma unroll
        for (int n = 0; n < 2; n++) {
            float2 bv = *reinterpret_cast<const float2*>(&CN[C_B1 + wc * 16 + n * 8 + 2 * t4]);
            #pragma unroll
            for (int mi = 0; mi < 2; mi++) {
                acc1[mi][n][0] = bv.x; acc1[mi][n][1] = bv.y;
                acc1[mi][n][2] = bv.x; acc1[mi][n][3] = bv.y;
            }
        }
        {
            unsigned ab = su32(A1h) + (a_row * SA + a_kof) * 2;
            unsigned bb = su32(W1h) + (b_kof * SW1 + wc * 16 + b_cof) * 2;
            #pragma unroll
            for (int kk = 0; kk < 3; kk++) {
                unsigned a[2][4], b[4];
                LDM_X4(a[0], ab + (kk * 16) * 2);
                LDM_X4(a[1], ab + (16 * SA + kk * 16) * 2);
                LDM_X4T(b, bb + (kk * 16 * SW1) * 2);
                #pragma unroll
                for (int n = 0; n < 2; n++) {
                    MMA_F16(acc1[0][n], a[0], b[n * 2], b[n * 2 + 1]);
                    MMA_F16(acc1[1][n], a[1], b[n * 2], b[n * 2 + 1]);
                }
            }
        }

        // ---- epilogue1: fast GELU -> fp16 H (+ keep own A-fragment in regs) ----
        unsigned a_self[2][4];
        #pragma unroll
        for (int mi = 0; mi < 2; mi++) {
            int r = mi * 16 + g;
            #pragma unroll
            for (int n = 0; n < 2; n++) {
                int c = wc * 16 + n * 8 + 2 * t4;
                __half2 hlo = __floats2half2_rn(gelu_fast(acc1[mi][n][0]), gelu_fast(acc1[mi][n][1]));
                __half2 hhi = __floats2half2_rn(gelu_fast(acc1[mi][n][2]), gelu_fast(acc1[mi][n][3]));
                *(__half2*)&Hh[r * SHH + c]       = hlo;
                *(__half2*)&Hh[(r + 8) * SHH + c] = hhi;
                a_self[mi][n * 2 + 0] = *(unsigned*)&hlo;
                a_self[mi][n * 2 + 1] = *(unsigned*)&hhi;
            }
        }
        BARG(bid);   // Hh ready

        // ---- GEMM2: [32x128] x [128x256], 32 cols/warp (bias folded) ----
        // Chunk kk==wc: A-fragment comes straight from a_self (this warp made it).
        float acc2[2][4][4];
        #pragma unroll
        for (int n = 0; n < 4; n++) {
            float2 bv = *reinterpret_cast<const float2*>(&CN[C_B2 + wc * 32 + n * 8 + 2 * t4]);
            #pragma unroll
            for (int mi = 0; mi < 2; mi++) {
                acc2[mi][n][0] = bv.x; acc2[mi][n][1] = bv.y;
                acc2[mi][n][2] = bv.x; acc2[mi][n][3] = bv.y;
            }
        }
        {
            unsigned ab = su32(Hh)  + (a_row * SHH + a_kof) * 2;
            unsigned bb = su32(W2h) + (b_kof * SW2 + wc * 32 + b_cof) * 2;
            #pragma unroll 4
            for (int kk = 0; kk < 8; kk++) {
                unsigned a[2][4], b[2][4];
                if (kk == wc) {
                    #pragma unroll
                    for (int j = 0; j < 4; j++) { a[0][j] = a_self[0][j]; a[1][j] = a_self[1][j]; }
                } else {
                    LDM_X4(a[0], ab + (kk * 16) * 2);
                    LDM_X4(a[1], ab + (16 * SHH + kk * 16) * 2);
                }
                LDM_X4T(b[0], bb + (kk * 16 * SW2) * 2);
                LDM_X4T(b[1], bb + (kk * 16 * SW2 + 16) * 2);
                #pragma unroll
                for (int n = 0; n < 4; n++) {
                    int pp = n >> 1, qf = (n & 1) * 2;
                    MMA_F16(acc2[0][n], a[0], b[pp][qf], b[pp][qf + 1]);
                    MMA_F16(acc2[1][n], a[1], b[pp][qf], b[pp][qf + 1]);
                }
            }
        }

        // ---- LN2 partial sums (reduce over t4, stash per warp-col) ----
        #pragma unroll
        for (int mi = 0; mi < 2; mi++) {
            float s0 = 0.f, q0 = 0.f, s1 = 0.f, q1 = 0.f;
            #pragma unroll
            for (int n = 0; n < 4; n++) {
                float a0 = acc2[mi][n][0], a1 = acc2[mi][n][1];
                float a2 = acc2[mi][n][2], a3 = acc2[mi][n][3];
                s0 += a0 + a1; q0 += a0 * a0 + a1 * a1;
                s1 += a2 + a3; q1 += a2 * a2 + a3 * a3;
            }
            #pragma unroll
            for (int off = 1; off <= 2; off <<= 1) {
                s0 += __shfl_xor_sync(0xffffffffu, s0, off);
                q0 += __shfl_xor_sync(0xffffffffu, q0, off);
                s1 += __shfl_xor_sync(0xffffffffu, s1, off);
                q1 += __shfl_xor_sync(0xffffffffu, q1, off);
            }
            if (t4 == 0) {
                int r = mi * 16 + g;
                PS[r * 8 + wc]       = make_float2(s0, q0);
                PS[(r + 8) * 8 + wc] = make_float2(s1, q1);
            }
        }
        BARG(bid);   // PS ready

        // ---- epilogue2: mu/rstd via float4 PS reads, streaming stores ----
        float* outp = out + (size_t)tile * TILE_M * 256;
        float mu_[4], rs_[4];
        #pragma unroll
        for (int mi = 0; mi < 2; mi++) {
            #pragma unroll
            for (int h = 0; h < 2; h++) {
                int r = mi * 16 + g + h * 8;
                float s = 0.f, q = 0.f;
                #pragma unroll
                for (int pc4 = 0; pc4 < 4; pc4++) {
                    float4 v = PS4[r * 4 + pc4];     // two (s,q) partials
                    s += v.x + v.z; q += v.y + v.w;
                }
                float mu  = s * (1.0f / 256.0f);
                float var = q * (1.0f / 256.0f) - mu * mu;
                mu_[mi * 2 + h] = mu;
                rs_[mi * 2 + h] = rsqrtf(fmaxf(var, 0.f) + 1e-5f);
            }
        }
        #pragma unroll
        for (int n = 0; n < 4; n++) {
            int c = wc * 32 + n * 8 + 2 * t4;
            float2 gv = *reinterpret_cast<const float2*>(&CN[C_G2 + c]);
            float2 bv = *reinterpret_cast<const float2*>(&CN[C_BB2 + c]);
            #pragma unroll
            for (int mi = 0; mi < 2; mi++) {
                #pragma unroll
                for (int h = 0; h < 2; h++) {
                    int r = mi * 16 + g + h * 8;
                    float mu = mu_[mi * 2 + h], rstd = rs_[mi * 2 + h];
                    float v0 = acc2[mi][n][h * 2 + 0];
                    float v1 = acc2[mi][n][h * 2 + 1];
                    float2 o;
                    o.x = (v0 - mu) * rstd * gv.x + bv.x;
                    o.y = (v1 - mu) * rstd * gv.y + bv.y;
                    __stcs(reinterpret_cast<float2*>(&outp[(size_t)r * 256 + c]), o);
                }
            }
        }

        // ---- LN1 for next tile (overlaps STGs above) ----
        if (tn < ntiles) {
            const float* row = pose + ((size_t)tn * TILE_M + ln_r) * 45;
            float x[6]; float s = 0.f, q = 0.f;
            #pragma unroll
            for (int j = 0; j < 6; j++) {
                int c = ln_c0 + j;
                x[j] = (c < 45) ? row[c] : 0.f;
                s += x[j]; q += x[j] * x[j];
            }
            #pragma unroll
            for (int off = 1; off <= 4; off <<= 1) {
                s += __shfl_xor_sync(0xffffffffu, s, off);
                q += __shfl_xor_sync(0xffffffffu, q, off);
            }
            float mu   = s * (1.0f / 45.0f);
            float var  = q * (1.0f / 45.0f) - mu * mu;
            float rstd = rsqrtf(fmaxf(var, 0.f) + 1e-5f);
            __half2* dstp = (__half2*)&A1h[ln_r * SA + ln_c0];
            #pragma unroll
            for (int j2 = 0; j2 < 3; j2++) {
                dstp[j2] = __floats2half2_rn((x[2*j2]   - mu) * rstd,
                                             (x[2*j2+1] - mu) * rstd);
            }
        }
    }
}

extern "C" void kernel_launch(void* const* d_in, const int* in_sizes, int n_in,
                              void* d_out, int out_size)
{
    const float* pose = (const float*)d_in[0];
    const float* ln1g = (const float*)d_in[1];
    const float* ln1b = (const float*)d_in[2];
    const float* w1   = (const float*)d_in[3];
    const float* b1   = (const float*)d_in[4];
    const float* w2   = (const float*)d_in[5];
    const float* b2   = (const float*)d_in[6];
    const float* ln2g = (const float*)d_in[7];
    const float* ln2b = (const float*)d_in[8];
    float* out = (float*)d_out;

    int nrows  = in_sizes[0] / 45;
    int ntiles = nrows / TILE_M;

    int dev = 0;
    cudaGetDevice(&dev);
    int nsm = 148;
    cudaDeviceGetAttribute(&nsm, cudaDevAttrMultiProcessorCount, dev);

    cudaFuncSetAttribute(pose_mlp_kernel,
                         cudaFuncAttributeMaxDynamicSharedMemorySize, SMEM_BYTES);

    int grid = nsm;
    int need = (ntiles + NGROUPS - 1) / NGROUPS;
    if (grid > need) grid = need;
    pose_mlp_kernel<<<grid, NTHREADS, SMEM_BYTES>>>(
        pose, ln1g, ln1b, w1, b1, w2, b2, ln2g, ln2b, out, ntiles);
}

// round 16
// speedup vs baseline: 1.0086x; 1.0086x over previous
#include <cuda_runtime.h>
#include <cuda_fp16.h>
#include <cstdint>

#define NTHREADS 1024
#define TILE_M   32
#define NGROUPS  4

// half-element strides (conflict-free ldmatrix / stores)
#define SW2 264   // W2h [128][256+pad]
#define SW1 136   // W1h [48][128+pad]
#define SA   56   // A1h [32][48+pad]
#define SHH 136   // Hh  [32][128+pad]

// smem byte offsets
#define OFF_W2   0              // 128*264*2 = 67584
#define OFF_W1   67584          // 48*136*2  = 13056
#define OFF_GRP  80640          // per-group region base
#define G_A1     0              // 3584 B
#define G_H      3584           // 8704 B
#define G_PS     12288          // 2048 B
#define GRP_SZ   14336
#define OFF_CN   137984         // 992 floats = 3968 B
#define SMEM_BYTES 141952

// CN float offsets
#define C_B1  96
#define C_B2  224
#define C_G2  480
#define C_BB2 736

__device__ __forceinline__ unsigned su32(const void* p) {
    return (unsigned)__cvta_generic_to_shared(p);
}

// tanh-based GELU: HW tanh.approx; error << fp16 rounding of H
__device__ __forceinline__ float gelu_fast(float x) {
    float u = 0.7978845608028654f * fmaf(0.044715f * x, x * x, x);
    float t;
    asm("tanh.approx.f32 %0, %1;" : "=f"(t) : "f"(u));
    return 0.5f * x * (1.0f + t);
}

#define LDM_X4(R, addr)                                                        \
    asm volatile("ldmatrix.sync.aligned.m8n8.x4.shared.b16 {%0,%1,%2,%3}, [%4];" \
        : "=r"((R)[0]), "=r"((R)[1]), "=r"((R)[2]), "=r"((R)[3]) : "r"(addr))

#define LDM_X4T(R, addr)                                                       \
    asm volatile("ldmatrix.sync.aligned.m8n8.x4.trans.shared.b16 {%0,%1,%2,%3}, [%4];" \
        : "=r"((R)[0]), "=r"((R)[1]), "=r"((R)[2]), "=r"((R)[3]) : "r"(addr))

#define MMA_F16(C, A, b0, b1)                                                  \
    asm volatile("mma.sync.aligned.m16n8k16.row.col.f32.f16.f16.f32 "          \
        "{%0,%1,%2,%3}, {%4,%5,%6,%7}, {%8,%9}, {%0,%1,%2,%3};"                \
        : "+f"((C)[0]), "+f"((C)[1]), "+f"((C)[2]), "+f"((C)[3])               \
        : "r"((A)[0]), "r"((A)[1]), "r"((A)[2]), "r"((A)[3]), "r"(b0), "r"(b1))

// group-scoped barrier: 256 threads, ids 1..4
#define BARG(id) asm volatile("bar.sync %0, 256;" :: "r"(id) : "memory")

__global__ void __launch_bounds__(NTHREADS, 1)
pose_mlp_kernel(const float* __restrict__ pose,
                const float* __restrict__ ln1g, const float* __restrict__ ln1b,
                const float* __restrict__ w1,   const float* __restrict__ b1,
                const float* __restrict__ w2,   const float* __restrict__ b2,
                const float* __restrict__ ln2g, const float* __restrict__ ln2b,
                float* __restrict__ out, int ntiles)
{
    extern __shared__ char smem[];
    __half* W2h = (__half*)(smem + OFF_W2);
    __half* W1h = (__half*)(smem + OFF_W1);
    float*  CN  = (float*)(smem + OFF_CN);

    const int tid  = threadIdx.x;
    const int lane = tid & 31;
    const int warp = tid >> 5;
    const int gr   = warp >> 3;           // pipeline group 0..3
    const int wc   = warp & 7;            // warp col (8), Wr = 1
    const int tid2 = tid & 255;           // thread within group
    const int g    = lane >> 2;
    const int t4   = lane & 3;
    const int bid  = gr + 1;              // named barrier id

    char* gbase = smem + OFF_GRP + gr * GRP_SZ;
    __half* A1h = (__half*)(gbase + G_A1);
    __half* Hh  = (__half*)(gbase + G_H);
    float2* PS  = (float2*)(gbase + G_PS);
    const float4* PS4 = (const float4*)(gbase + G_PS);

    const int lm_m  = lane >> 3;
    const int lm_r  = lane & 7;
    const int a_row = lm_r + (lm_m & 1) * 8;
    const int a_kof = (lm_m >> 1) * 8;
    const int b_kof = lm_r + (lm_m & 1) * 8;
    const int b_cof = (lm_m >> 1) * 8;

    // LN1: 8 threads per row (within group), 6 cols each
    const int ln_r  = tid2 >> 3;
    const int ln_c0 = (tid2 & 7) * 6;

    // ---- one-time: weights + consts -> smem (whole CTA) ----
    for (int i = tid; i < 8192; i += NTHREADS) {            // W2 via float4
        int k = i >> 6;
        int c = (i & 63) << 2;
        float4 v = reinterpret_cast<const float4*>(w2)[i];
        __half2* d = (__half2*)&W2h[k * SW2 + c];
        d[0] = __floats2half2_rn(v.x, v.y);
        d[1] = __floats2half2_rn(v.z, v.w);
    }
    for (int i = tid; i < 48 * 128; i += NTHREADS) {        // W1 (gamma-folded), rows 45..47 zero
        int k = i >> 7;
        int c = i & 127;
        W1h[k * SW1 + c] = (k < 45) ? __float2half_rn(ln1g[k] * w1[k * 128 + c])
                                    : __float2half_rn(0.0f);
    }
    if (tid < 128) {                                        // b1' = b1 + ln1b . W1
        float acc = b1[tid];
        for (int k = 0; k < 45; k++) acc += ln1b[k] * w1[k * 128 + tid];
        CN[C_B1 + tid] = acc;
    }
    if (tid >= 128 && tid < 384) {
        int i = tid - 128;
        CN[C_B2 + i] = b2[i]; CN[C_G2 + i] = ln2g[i]; CN[C_BB2 + i] = ln2b[i];
    }
    __syncthreads();   // only CTA-wide barrier; groups independent after this

    const int stride = NGROUPS * gridDim.x;
    int tile = blockIdx.x * NGROUPS + gr;

    // ---- prologue LN1 (gmem -> A1h), gamma/beta folded into W1/b1' ----
    if (tile < ntiles) {
        const float* row = pose + ((size_t)tile * TILE_M + ln_r) * 45;
        float x[6]; float s = 0.f, q = 0.f;
        #pragma unroll
        for (int j = 0; j < 6; j++) {
            int c = ln_c0 + j;
            x[j] = (c < 45) ? row[c] : 0.f;
            s += x[j]; q += x[j] * x[j];
        }
        #pragma unroll
        for (int off = 1; off <= 4; off <<= 1) {
            s += __shfl_xor_sync(0xffffffffu, s, off);
            q += __shfl_xor_sync(0xffffffffu, q, off);
        }
        float mu   = s * (1.0f / 45.0f);
        float var  = q * (1.0f / 45.0f) - mu * mu;
        float rstd = rsqrtf(fmaxf(var, 0.f) + 1e-5f);
        __half2* dstp = (__half2*)&A1h[ln_r * SA + ln_c0];
        #pragma unroll
        for (int j2 = 0; j2 < 3; j2++) {
            dstp[j2] = __floats2half2_rn((x[2*j2]   - mu) * rstd,
                                         (x[2*j2+1] - mu) * rstd);
        }
    }

    for (; tile < ntiles; tile += stride) {
        const int tn = tile + stride;
        BARG(bid);   // A1h ready

        // ---- GEMM1: [32x48] x [48x128], 16 cols/warp (bias folded) ----
        float acc1[2][2][4];
        #pragma unroll
        for (int n = 0; n < 2; n++) {
            float2 bv = *reinterpret_cast<const float2*>(&CN[C_B1 + wc * 16 + n * 8 + 2 * t4]);
            #pragma unroll
            for (int mi = 0; mi < 2; mi++) {
                acc1[mi][n][0] = bv.x; acc1[mi][n][1] = bv.y;
                acc1[mi][n][2] = bv.x; acc1[mi][n][3] = bv.y;
            }
        }
        {
            unsigned ab = su32(A1h) + (a_row * SA + a_kof) * 2;
            unsigned bb = su32(W1h) + (b_kof * SW1 + wc * 16 + b_cof) * 2;
            #pragma unroll
            for (int kk = 0; kk < 3; kk++) {
                unsigned a[2][4], b[4];
                LDM_X4(a[0], ab + (kk * 16) * 2);
                LDM_X4(a[1], ab + (16 * SA + kk * 16) * 2);
                LDM_X4T(b, bb + (kk * 16 * SW1) * 2);
                #pragma unroll
                for (int n = 0; n < 2; n++) {
                    MMA_F16(acc1[0][n], a[0], b[n * 2], b[n * 2 + 1]);
                    MMA_F16(acc1[1][n], a[1], b[n * 2], b[n * 2 + 1]);
                }
            }
        }

        // ---- epilogue1: fast GELU -> fp16 H (+ keep own A-fragment in regs) ----
        unsigned a_self[2][4];
        #pragma unroll
        for (int mi = 0; mi < 2; mi++) {
            int r = mi * 16 + g;
            #pragma unroll
            for (int n = 0; n < 2; n++) {
                int c = wc * 16 + n * 8 + 2 * t4;
                __half2 hlo = __floats2half2_rn(gelu_fast(acc1[mi][n][0]), gelu_fast(acc1[mi][n][1]));
                __half2 hhi = __floats2half2_rn(gelu_fast(acc1[mi][n][2]), gelu_fast(acc1[mi][n][3]));
                *(__half2*)&Hh[r * SHH + c]       = hlo;
                *(__half2*)&Hh[(r + 8) * SHH + c] = hhi;
                a_self[mi][n * 2 + 0] = *(unsigned*)&hlo;
                a_self[mi][n * 2 + 1] = *(unsigned*)&hhi;
            }
        }
        BARG(bid);   // Hh ready

        // ---- GEMM2: rotated schedule; chunk wc peeled with A from regs ----
        float acc2[2][4][4];
        #pragma unroll
        for (int n = 0; n < 4; n++) {
            float2 bv = *reinterpret_cast<const float2*>(&CN[C_B2 + wc * 32 + n * 8 + 2 * t4]);
            #pragma unroll
            for (int mi = 0; mi < 2; mi++) {
                acc2[mi][n][0] = bv.x; acc2[mi][n][1] = bv.y;
                acc2[mi][n][2] = bv.x; acc2[mi][n][3] = bv.y;
            }
        }
        {
            unsigned ab = su32(Hh)  + (a_row * SHH + a_kof) * 2;
            unsigned bb = su32(W2h) + (b_kof * SW2 + wc * 32 + b_cof) * 2;
            // peeled chunk kk = wc: A from a_self (no ldmatrix, no wait)
            {
                unsigned b[2][4];
                unsigned bo = bb + (unsigned)(wc * 16 * SW2) * 2;
                LDM_X4T(b[0], bo);
                LDM_X4T(b[1], bo + 16 * 2);
                #pragma unroll
                for (int n = 0; n < 4; n++) {
                    int pp = n >> 1, qf = (n & 1) * 2;
                    MMA_F16(acc2[0][n], a_self[0], b[pp][qf], b[pp][qf + 1]);
                    MMA_F16(acc2[1][n], a_self[1], b[pp][qf], b[pp][qf + 1]);
                }
            }
            // remaining 7 chunks, rotated: kk = (wc + j) & 7
            #pragma unroll 7
            for (int j = 1; j < 8; j++) {
                int kk = (wc + j) & 7;
                unsigned a[2][4], b[2][4];
                LDM_X4(a[0], ab + (unsigned)(kk * 16) * 2);
                LDM_X4(a[1], ab + (unsigned)(16 * SHH + kk * 16) * 2);
                unsigned bo = bb + (unsigned)(kk * 16 * SW2) * 2;
                LDM_X4T(b[0], bo);
                LDM_X4T(b[1], bo + 16 * 2);
                #pragma unroll
                for (int n = 0; n < 4; n++) {
                    int pp = n >> 1, qf = (n & 1) * 2;
                    MMA_F16(acc2[0][n], a[0], b[pp][qf], b[pp][qf + 1]);
                    MMA_F16(acc2[1][n], a[1], b[pp][qf], b[pp][qf + 1]);
                }
            }
        }

        // ---- LN2 partial sums (reduce over t4, stash per warp-col) ----
        #pragma unroll
        for (int mi = 0; mi < 2; mi++) {
            float s0 = 0.f, q0 = 0.f, s1 = 0.f, q1 = 0.f;
            #pragma unroll
            for (int n = 0; n < 4; n++) {
                float a0 = acc2[mi][n][0], a1 = acc2[mi][n][1];
                float a2 = acc2[mi][n][2], a3 = acc2[mi][n][3];
                s0 += a0 + a1; q0 += a0 * a0 + a1 * a1;
                s1 += a2 + a3; q1 += a2 * a2 + a3 * a3;
            }
            #pragma unroll
            for (int off = 1; off <= 2; off <<= 1) {
                s0 += __shfl_xor_sync(0xffffffffu, s0, off);
                q0 += __shfl_xor_sync(0xffffffffu, q0, off);
                s1 += __shfl_xor_sync(0xffffffffu, s1, off);
                q1 += __shfl_xor_sync(0xffffffffu, q1, off);
            }
            if (t4 == 0) {
                int r = mi * 16 + g;
                PS[r * 8 + wc]       = make_float2(s0, q0);
                PS[(r + 8) * 8 + wc] = make_float2(s1, q1);
            }
        }
        BARG(bid);   // PS ready

        // ---- epilogue2: mu/rstd via float4 PS reads, streaming stores ----
        float* outp = out + (size_t)tile * TILE_M * 256;
        float mu_[4], rs_[4];
        #pragma unroll
        for (int mi = 0; mi < 2; mi++) {
            #pragma unroll
            for (int h = 0; h < 2; h++) {
                int r = mi * 16 + g + h * 8;
                float s = 0.f, q = 0.f;
                #pragma unroll
                for (int pc4 = 0; pc4 < 4; pc4++) {
                    float4 v = PS4[r * 4 + pc4];     // two (s,q) partials
                    s += v.x + v.z; q += v.y + v.w;
                }
                float mu  = s * (1.0f / 256.0f);
                float var = q * (1.0f / 256.0f) - mu * mu;
                mu_[mi * 2 + h] = mu;
                rs_[mi * 2 + h] = rsqrtf(fmaxf(var, 0.f) + 1e-5f);
            }
        }
        #pragma unroll
        for (int n = 0; n < 4; n++) {
            int c = wc * 32 + n * 8 + 2 * t4;
            float2 gv = *reinterpret_cast<const float2*>(&CN[C_G2 + c]);
            float2 bv = *reinterpret_cast<const float2*>(&CN[C_BB2 + c]);
            #pragma unroll
            for (int mi = 0; mi < 2; mi++) {
                #pragma unroll
                for (int h = 0; h < 2; h++) {
                    int r = mi * 16 + g + h * 8;
                    float mu = mu_[mi * 2 + h], rstd = rs_[mi * 2 + h];
                    float v0 = acc2[mi][n][h * 2 + 0];
                    float v1 = acc2[mi][n][h * 2 + 1];
                    float2 o;
                    o.x = (v0 - mu) * rstd * gv.x + bv.x;
                    o.y = (v1 - mu) * rstd * gv.y + bv.y;
                    __stcs(reinterpret_cast<float2*>(&outp[(size_t)r * 256 + c]), o);
                }
            }
        }

        // ---- LN1 for next tile (overlaps STGs above) ----
        if (tn < ntiles) {
            const float* row = pose + ((size_t)tn * TILE_M + ln_r) * 45;
            float x[6]; float s = 0.f, q = 0.f;
            #pragma unroll
            for (int j = 0; j < 6; j++) {
                int c = ln_c0 + j;
                x[j] = (c < 45) ? row[c] : 0.f;
                s += x[j]; q += x[j] * x[j];
            }
            #pragma unroll
            for (int off = 1; off <= 4; off <<= 1) {
                s += __shfl_xor_sync(0xffffffffu, s, off);
                q += __shfl_xor_sync(0xffffffffu, q, off);
            }
            float mu   = s * (1.0f / 45.0f);
            float var  = q * (1.0f / 45.0f) - mu * mu;
            float rstd = rsqrtf(fmaxf(var, 0.f) + 1e-5f);
            __half2* dstp = (__half2*)&A1h[ln_r * SA + ln_c0];
            #pragma unroll
            for (int j2 = 0; j2 < 3; j2++) {
                dstp[j2] = __floats2half2_rn((x[2*j2]   - mu) * rstd,
                                             (x[2*j2+1] - mu) * rstd);
            }
        }
    }
}

extern "C" void kernel_launch(void* const* d_in, const int* in_sizes, int n_in,
                              void* d_out, int out_size)
{
    const float* pose = (const float*)d_in[0];
    const float* ln1g = (const float*)d_in[1];
    const float* ln1b = (const float*)d_in[2];
    const float* w1   = (const float*)d_in[3];
    const float* b1   = (const float*)d_in[4];
    const float* w2   = (const float*)d_in[5];
    const float* b2   = (const float*)d_in[6];
    const float* ln2g = (const float*)d_in[7];
    const float* ln2b = (const float*)d_in[8];
    float* out = (float*)d_out;

    int nrows  = in_sizes[0] / 45;
    int ntiles = nrows / TILE_M;

    int dev = 0;
    cudaGetDevice(&dev);
    int nsm = 148;
    cudaDeviceGetAttribute(&nsm, cudaDevAttrMultiProcessorCount, dev);

    cudaFuncSetAttribute(pose_mlp_kernel,
                         cudaFuncAttributeMaxDynamicSharedMemorySize, SMEM_BYTES);

    int grid = nsm;
    int need = (ntiles + NGROUPS - 1) / NGROUPS;
    if (grid > need) grid = need;
    pose_mlp_kernel<<<grid, NTHREADS, SMEM_BYTES>>>(
        pose, ln1g, ln1b, w1, b1, w2, b2, ln2g, ln2b, out, ntiles);
}